// round 1
// baseline (speedup 1.0000x reference)
#include <cuda_runtime.h>

typedef unsigned long long u64;

#define B_ 4096
#define T_ 128
#define I_ 16
#define H_ 64
#define G_ 192   // 3*H threads per block: one per (gate, hidden-unit) row

// ---- packed f32x2 helpers (sm_100+ only; ptxas never emits these from C++) ----
__device__ __forceinline__ u64 pk2(float lo, float hi) {
    u64 r; asm("mov.b64 %0, {%1,%2};" : "=l"(r) : "f"(lo), "f"(hi)); return r;
}
__device__ __forceinline__ void upk2(u64 v, float& lo, float& hi) {
    asm("mov.b64 {%0,%1}, %2;" : "=f"(lo), "=f"(hi) : "l"(v));
}
__device__ __forceinline__ u64 fma2(u64 a, u64 b, u64 c) {
    u64 d; asm("fma.rn.f32x2 %0, %1, %2, %3;" : "=l"(d) : "l"(a), "l"(b), "l"(c)); return d;
}
__device__ __forceinline__ u64 add2(u64 a, u64 b) {
    u64 d; asm("add.rn.f32x2 %0, %1, %2;" : "=l"(d) : "l"(a), "l"(b)); return d;
}

// exp-based activations: __expf has ~2-ulp error (tanh.approx's 2^-11 would
// compound over 128 recurrent steps; this stays ~1e-6/step).
__device__ __forceinline__ float sigmoidf_(float a) {
    return __fdividef(1.0f, 1.0f + __expf(-a));
}
__device__ __forceinline__ float tanhf_(float a) {
    return __fdividef(2.0f, 1.0f + __expf(-2.0f * a)) - 1.0f;
}

__global__ __launch_bounds__(G_) void gru_fused_kernel(
    const float* __restrict__ x,     // [B, T, I]
    const float* __restrict__ w_ih,  // [3H, I]
    const float* __restrict__ w_hh,  // [3H, H]
    const float* __restrict__ b_ih,  // [3H]
    const float* __restrict__ b_hh,  // [3H]
    const float* __restrict__ fc_w,  // [1, H]
    const float* __restrict__ fc_b,  // [1]
    float* __restrict__ out)         // [B]
{
    // x slice for this batch element, stored as packed f32x2 pairs along I
    __shared__ __align__(16) u64 sx[T_ * I_ / 2];   // 1024 u64 = 8 KB
    __shared__ __align__(16) u64 sh[H_ / 2];        // hidden state, packed pairs
    __shared__ float sr[H_];
    __shared__ float sz[H_];

    const int g = threadIdx.x;          // gate-row 0..191 (r: 0-63, z: 64-127, n: 128-191)
    const int b = blockIdx.x;           // batch element
    const int j = g & (H_ - 1);         // hidden unit within role
    const int role = g >> 6;            // 0=r, 1=z, 2=n

    // ---- preload this batch's x slice (coalesced, 8 KB) ----
    const u64* gx = reinterpret_cast<const u64*>(x + (size_t)b * T_ * I_);
    for (int i = g; i < T_ * I_ / 2; i += G_) sx[i] = gx[i];
    if (g < H_ / 2) sh[g] = 0ull;       // h0 = 0

    // ---- register-resident weights for this thread's gate-row ----
    u64 whh[H_ / 2];                    // 32 x u64 = 64 fp32 coefficients
    {
        const u64* wr = reinterpret_cast<const u64*>(w_hh + g * H_);
        #pragma unroll
        for (int k = 0; k < H_ / 2; k++) whh[k] = wr[k];
    }
    u64 wih[I_ / 2];                    // 8 x u64 = 16 fp32 coefficients
    {
        const u64* wr = reinterpret_cast<const u64*>(w_ih + g * I_);
        #pragma unroll
        for (int k = 0; k < I_ / 2; k++) wih[k] = wr[k];
    }
    const float bi = b_ih[g];
    const float bh = b_hh[g];

    __syncthreads();

    const ulonglong2* sh4 = reinterpret_cast<const ulonglong2*>(sh);
    float* shf = reinterpret_cast<float*>(sh);

    for (int t = 0; t < T_; t++) {
        // ---- input-gate contribution: xa = w_ih[g,:] . x_t + b_ih[g] (2 chains)
        u64 xa0 = pk2(bi, 0.0f);
        u64 xa1 = pk2(0.0f, 0.0f);
        const ulonglong2* xt = reinterpret_cast<const ulonglong2*>(sx + t * (I_ / 2));
        #pragma unroll
        for (int m = 0; m < I_ / 4; m++) {
            ulonglong2 v = xt[m];                       // LDS.128 broadcast
            xa0 = fma2(wih[2 * m + 0], v.x, xa0);
            xa1 = fma2(wih[2 * m + 1], v.y, xa1);
        }
        // ---- recurrent contribution: ha = w_hh[g,:] . h + b_hh[g] (4 chains)
        u64 ha0 = pk2(bh, 0.0f), ha1 = pk2(0.0f, 0.0f);
        u64 ha2 = pk2(0.0f, 0.0f), ha3 = pk2(0.0f, 0.0f);
        #pragma unroll
        for (int m = 0; m < H_ / 8; m++) {              // 8 iters, 4 FFMA2 each
            ulonglong2 v0 = sh4[2 * m + 0];             // LDS.128 broadcast
            ulonglong2 v1 = sh4[2 * m + 1];
            ha0 = fma2(whh[4 * m + 0], v0.x, ha0);
            ha1 = fma2(whh[4 * m + 1], v0.y, ha1);
            ha2 = fma2(whh[4 * m + 2], v1.x, ha2);
            ha3 = fma2(whh[4 * m + 3], v1.y, ha3);
        }
        float xlo, xhi, hlo, hhi;
        upk2(add2(xa0, xa1), xlo, xhi);
        upk2(add2(add2(ha0, ha1), add2(ha2, ha3)), hlo, hhi);
        const float xa = xlo + xhi;     // x-part + b_ih  (gi)
        const float ha = hlo + hhi;     // h-part + b_hh  (hg)

        if (role < 2) {                 // r and z gates: plain sigmoid of sum
            float v = sigmoidf_(xa + ha);
            if (role == 0) sr[j] = v; else sz[j] = v;
        }
        __syncthreads();                // r,z published; all h reads of phase A done
        if (role == 2) {                // n gate + state update
            float r    = sr[j];
            float n    = tanhf_(xa + r * ha);   // tanh(gi_n + r * hn)
            float z    = sz[j];
            float hold = shf[j];
            shf[j]     = n + z * (hold - n);    // (1-z)*n + z*h
        }
        __syncthreads();                // h_new visible for next step
    }

    // ---- linear head: out[b] = h_T . fc_w + fc_b ----
    if (role == 0) sr[j] = shf[j] * fc_w[j];
    __syncthreads();
    if (g == 0) {
        float s = fc_b[0];
        #pragma unroll
        for (int k = 0; k < H_; k++) s += sr[k];
        out[b] = s;
    }
}

extern "C" void kernel_launch(void* const* d_in, const int* in_sizes, int n_in,
                              void* d_out, int out_size) {
    const float* x    = (const float*)d_in[0];
    const float* w_ih = (const float*)d_in[1];
    const float* w_hh = (const float*)d_in[2];
    const float* b_ih = (const float*)d_in[3];
    const float* b_hh = (const float*)d_in[4];
    const float* fc_w = (const float*)d_in[5];
    const float* fc_b = (const float*)d_in[6];
    float* out = (float*)d_out;

    gru_fused_kernel<<<B_, G_>>>(x, w_ih, w_hh, b_ih, b_hh, fc_w, fc_b, out);
}